// round 15
// baseline (speedup 1.0000x reference)
#include <cuda_runtime.h>
#include <cstdint>
#include <cstddef>

#define C_DIM 256
#define H_DIM 96
#define W_DIM 96
#define TW 16
#define TH 8
#define NPAIR 2
#define RAD 4
#define CC 8
#define NSTAGE (C_DIM / CC)                  // 32
#define S1_ROW 16
#define S1_CH  (TH * S1_ROW)                 // 128
#define S1_WORDS (CC * S1_CH)                // 1024
#define S2_ROWS (TH + 8)                     // 16
#define S2_ROW 32                            // 24 data words in 8 swizzled 16B slots
#define S2_CH  (S2_ROWS * S2_ROW)            // 512
#define S2_WORDS (CC * S2_CH)                // 4096
#define STAGE_WORDS (S1_WORDS + S2_WORDS)    // 5120
#define STAGE_BYTES (STAGE_WORDS * 4)        // 20480
#define NBUF 3
#define NTHREADS 288
#define CADV (CC * H_DIM * W_DIM)

typedef unsigned long long u64;

union F2U { float2 f2; u64 u; };

__device__ __forceinline__ void fma2(u64 &d, u64 a, u64 b) {
    asm("fma.rn.f32x2 %0, %1, %2, %0;" : "+l"(d) : "l"(a), "l"(b));
}
__device__ __forceinline__ void cp16(uint32_t s, const float* g, uint32_t vbit) {
    int sz = vbit ? 16 : 0;
    asm volatile("cp.async.cg.shared.global [%0], [%1], 16, %2;\n"
                 :: "r"(s), "l"(g), "r"(sz));
}

__global__ __launch_bounds__(NTHREADS, 3)
void corr_kernel(const float* __restrict__ in1, const float* __restrict__ in2,
                 float* __restrict__ out) {
    extern __shared__ float smem[];
    const int tid = threadIdx.x;
    const int w0 = blockIdx.x * TW;
    const int h0 = blockIdx.y * TH;
    const int b  = blockIdx.z;

    const int ph   = tid >> 5;          // warp id = displacement row 0..8
    const int lane = tid & 31;
    const int pc   = lane & 3;          // 4-px block 0..3
    const int r    = lane >> 2;         // tile row 0..7
    const int x0   = pc * 4;

    // ---- hoisted load addressing (256 loader threads, 4x 16B cp.async each) ----
    const bool loader = (tid < 256);
    const float* p1 = in1;
    const float* p2 = in2;
    uint32_t d1 = 0, mask = 0;
    uint32_t d2j[3] = {0, 0, 0};
    int adj = 0;
    if (loader) {
        const int c1   = tid >> 5;
        const int rem  = tid & 31;
        const int row1 = rem >> 2;
        const int q    = rem & 3;
        p1 = in1 + (((size_t)(b * C_DIM + c1) * H_DIM + (h0 + row1)) * W_DIM + w0 + q * 4);
        d1 = (uint32_t)((c1 * S1_CH + row1 * S1_ROW + q * 4) * 4);

        const int c2   = tid >> 5;
        const int rid  = tid & 31;
        const int y    = rid >> 1;
        const int half = rid & 1;
        const int h2   = h0 + y - RAD;
        const int col0 = w0 - RAD + half * 12;
        const bool hv  = (h2 >= 0) && (h2 < H_DIM);
        const int rot  = 4 * (y & 1);
#pragma unroll
        for (int j = 0; j < 3; j++) {
            int cg = col0 + 4 * j;
            if (hv && cg >= 0 && cg + 4 <= W_DIM) mask |= (1u << j);
            int slot = (3 * half + j + rot) & 7;   // rotation swizzle
            d2j[j] = (uint32_t)((S1_WORDS + c2 * S2_CH + y * S2_ROW + slot * 4) * 4);
        }
        const int wc = (col0 < 0) ? 0 : (col0 > W_DIM - 4 ? W_DIM - 4 : col0);
        adj = col0 - wc;
        p2 = in2 + (((size_t)(b * C_DIM + c2) * H_DIM + (hv ? h2 : 0)) * W_DIM + wc);
    }

    u64 accE[NPAIR][5];
    float accO[NPAIR][4][2];
#pragma unroll
    for (int k = 0; k < NPAIR; k++) {
#pragma unroll
        for (int d = 0; d < 5; d++) accE[k][d] = 0ull;
#pragma unroll
        for (int d = 0; d < 4; d++) { accO[k][d][0] = 0.f; accO[k][d][1] = 0.f; }
    }

    const uint32_t sb0 = (uint32_t)__cvta_generic_to_shared(smem);

    auto load_stage = [&](int buf) {
        if (loader) {
            const uint32_t sbase = sb0 + (uint32_t)(buf * STAGE_BYTES);
            cp16(sbase + d1, p1, 1u);
#pragma unroll
            for (int j = 0; j < 3; j++) {
                uint32_t v = (mask >> j) & 1u;
                const float* src = p2 + (v ? (4 * j + adj) : 0);
                cp16(sbase + d2j[j], src, v);
            }
            p1 += CADV;
            p2 += CADV;
        }
        asm volatile("cp.async.commit_group;\n");
    };

    load_stage(0);
    load_stage(1);

    // per-thread compute offsets (words)
    const int o1 = r * S1_ROW + x0;
    const int y0 = r + ph;
    const int rotc = 4 * (y0 & 1);
    int o2q[3];
#pragma unroll
    for (int q = 0; q < 3; q++)
        o2q[q] = S1_WORDS + y0 * S2_ROW + (((pc + q) + rotc) & 7) * 4;

    int bufc = 0;
    int bufl = 2;
    for (int s = 0; s < NSTAGE; s++) {
        if (s < NSTAGE - 1) {
            asm volatile("cp.async.wait_group 1;\n");
        } else {
            asm volatile("cp.async.wait_group 0;\n");
        }
        __syncthreads();
        if (s + 2 < NSTAGE) load_stage(bufl);

        const float* sp = smem + bufc * STAGE_WORDS;
#pragma unroll
        for (int cc = 0; cc < CC; cc++) {
            // in1: 4 px via one LDS.128 (conflict-free: starts 16r+4pc)
            float4 t1 = *(const float4*)(sp + cc * S1_CH + o1);
            F2U v1[NPAIR];
            v1[0].f2 = make_float2(t1.x, t1.y);
            v1[1].f2 = make_float2(t1.z, t1.w);

            // in2: 12-float span via 3 LDS.128 (rotation swizzle, conflict-free)
            F2U v2[6];
#pragma unroll
            for (int q = 0; q < 3; q++) {
                float4 t = *(const float4*)(sp + cc * S2_CH + o2q[q]);
                v2[2 * q].f2     = make_float2(t.x, t.y);
                v2[2 * q + 1].f2 = make_float2(t.z, t.w);
            }

            // even dw: packed FMA
#pragma unroll
            for (int k = 0; k < NPAIR; k++)
#pragma unroll
                for (int dh = 0; dh < 5; dh++)
                    fma2(accE[k][dh], v1[k].u, v2[k + dh].u);

            // odd dw: scalar FMAs on named halves
#pragma unroll
            for (int k = 0; k < NPAIR; k++)
#pragma unroll
                for (int dh = 0; dh < 4; dh++) {
                    accO[k][dh][0] = __fmaf_rn(v1[k].f2.x, v2[k + dh].f2.y, accO[k][dh][0]);
                    accO[k][dh][1] = __fmaf_rn(v1[k].f2.y, v2[k + dh + 1].f2.x, accO[k][dh][1]);
                }
        }

        bufc = (bufc == NBUF - 1) ? 0 : bufc + 1;
        bufl = (bufl == NBUF - 1) ? 0 : bufl + 1;
    }

    // epilogue
    const size_t plane = (size_t)H_DIM * W_DIM;
    float* op = out + (size_t)(b * 81 + ph * 9) * plane +
                (size_t)(h0 + r) * W_DIM + (w0 + x0);
#pragma unroll
    for (int dh = 0; dh < 5; dh++) {
        u64* orow = (u64*)(op + (size_t)(2 * dh) * plane);
#pragma unroll
        for (int k = 0; k < NPAIR; k++) orow[k] = accE[k][dh];
    }
#pragma unroll
    for (int dh = 0; dh < 4; dh++) {
        float* orow = op + (size_t)(2 * dh + 1) * plane;
#pragma unroll
        for (int k = 0; k < NPAIR; k++) {
            F2U t; t.f2.x = accO[k][dh][0]; t.f2.y = accO[k][dh][1];
            *(u64*)(orow + 2 * k) = t.u;
        }
    }
}

extern "C" void kernel_launch(void* const* d_in, const int* in_sizes, int n_in,
                              void* d_out, int out_size) {
    const float* in1 = (const float*)d_in[0];
    const float* in2 = (const float*)d_in[1];
    float* out = (float*)d_out;
    int Bn = in_sizes[0] / (C_DIM * H_DIM * W_DIM);
    size_t smem_bytes = (size_t)NBUF * STAGE_BYTES;  // 61440
    cudaFuncSetAttribute(corr_kernel, cudaFuncAttributeMaxDynamicSharedMemorySize,
                         (int)smem_bytes);
    dim3 grid(W_DIM / TW, H_DIM / TH, Bn);
    corr_kernel<<<grid, NTHREADS, smem_bytes>>>(in1, in2, out);
}

// round 16
// speedup vs baseline: 1.7448x; 1.7448x over previous
#include <cuda_runtime.h>
#include <cstdint>
#include <cstddef>

#define C_DIM 256
#define H_DIM 96
#define W_DIM 96
#define TW 16
#define TH 8
#define NPAIR 2
#define RAD 4
#define CC 4
#define NSTAGE (C_DIM / CC)                  // 64
#define S1_ROW 16
#define S1_CH  (TH * S1_ROW)                 // 128
#define S1_WORDS (CC * S1_CH)                // 512
#define S2_ROWS (TH + 8)                     // 16
#define S2_ROW 48                            // stride ≡ 16 mod 32 -> LDS.128 conflict-free
#define S2_CH  (S2_ROWS * S2_ROW)            // 768
#define S2_WORDS (CC * S2_CH)                // 3072
#define STAGE_WORDS (S1_WORDS + S2_WORDS)    // 3584
#define STAGE_BYTES (STAGE_WORDS * 4)        // 14336
#define NBUF 3
#define NTHREADS 288
#define CADV (CC * H_DIM * W_DIM)            // channel advance per stage (floats)

typedef unsigned long long u64;

union F2U { float2 f2; u64 u; };

__device__ __forceinline__ void fma2(u64 &d, u64 a, u64 b) {
    asm("fma.rn.f32x2 %0, %1, %2, %0;" : "+l"(d) : "l"(a), "l"(b));
}
__device__ __forceinline__ void cp16(uint32_t s, const float* g, uint32_t vbit) {
    int sz = vbit ? 16 : 0;
    asm volatile("cp.async.cg.shared.global [%0], [%1], 16, %2;\n"
                 :: "r"(s), "l"(g), "r"(sz));
}

__global__ __launch_bounds__(NTHREADS, 3)
void corr_kernel(const float* __restrict__ in1, const float* __restrict__ in2,
                 float* __restrict__ out) {
    extern __shared__ float smem[];
    const int tid = threadIdx.x;
    const int w0 = blockIdx.x * TW;
    const int h0 = blockIdx.y * TH;
    const int b  = blockIdx.z;

    const int ph   = tid >> 5;          // warp id = displacement row 0..8
    const int lane = tid & 31;
    const int pc   = lane & 3;          // 4-px block 0..3
    const int r    = lane >> 2;         // tile row 0..7
    const int x0   = pc * 4;

    // ---- hoisted load addressing ----
    // tid 0..127  : in2, 3x 16B chunks (half of one 24-float halo row)
    // tid 128..255: in1, 1x 16B chunk
    const bool l2ok = (tid < 128);
    const bool l1ok = (tid >= 128) && (tid < 256);
    const float* p1 = in1;
    const float* p2 = in2;
    uint32_t d1 = 0, d2 = 0, mask = 0;
    int adj = 0;
    if (l1ok) {
        const int t    = tid - 128;
        const int c1   = t >> 5;              // 0..3
        const int rem  = t & 31;
        const int row1 = rem >> 2;            // 0..7
        const int q    = rem & 3;             // 0..3
        p1 = in1 + (((size_t)(b * C_DIM + c1) * H_DIM + (h0 + row1)) * W_DIM + w0 + q * 4);
        d1 = (uint32_t)((c1 * S1_CH + row1 * S1_ROW + q * 4) * 4);
    }
    if (l2ok) {
        const int c2   = tid >> 5;            // 0..3
        const int rid  = tid & 31;
        const int y    = rid >> 1;            // 0..15
        const int half = rid & 1;
        const int h2   = h0 + y - RAD;
        const int col0 = w0 - RAD + half * 12;
        const bool hv  = (h2 >= 0) && (h2 < H_DIM);
#pragma unroll
        for (int j = 0; j < 3; j++) {
            int cg = col0 + 4 * j;
            if (hv && cg >= 0 && cg + 4 <= W_DIM) mask |= (1u << j);
        }
        const int wc = (col0 < 0) ? 0 : (col0 > W_DIM - 4 ? W_DIM - 4 : col0);
        adj = col0 - wc;
        p2 = in2 + (((size_t)(b * C_DIM + c2) * H_DIM + (hv ? h2 : 0)) * W_DIM + wc);
        d2 = (uint32_t)((S1_WORDS + c2 * S2_CH + y * S2_ROW + half * 12) * 4);
    }

    u64 accE[NPAIR][5];
    float accO[NPAIR][4][2];
#pragma unroll
    for (int k = 0; k < NPAIR; k++) {
#pragma unroll
        for (int d = 0; d < 5; d++) accE[k][d] = 0ull;
#pragma unroll
        for (int d = 0; d < 4; d++) { accO[k][d][0] = 0.f; accO[k][d][1] = 0.f; }
    }

    const uint32_t sb0 = (uint32_t)__cvta_generic_to_shared(smem);

    auto load_stage = [&](int buf) {
        const uint32_t sbase = sb0 + (uint32_t)(buf * STAGE_BYTES);
        if (l1ok) {
            cp16(sbase + d1, p1, 1u);
            p1 += CADV;
        }
        if (l2ok) {
#pragma unroll
            for (int j = 0; j < 3; j++) {
                uint32_t v = (mask >> j) & 1u;
                const float* src = p2 + (v ? (4 * j + adj) : 0);
                cp16(sbase + d2 + j * 16, src, v);
            }
            p2 += CADV;
        }
        asm volatile("cp.async.commit_group;\n");
    };

    load_stage(0);
    load_stage(1);

    // per-thread compute offsets (words) — immediates per channel
    const int o1 = r * S1_ROW + x0;
    const int y0 = r + ph;
    const int o2 = S1_WORDS + y0 * S2_ROW + x0;

    int bufc = 0;
    int bufl = 2;
    for (int s = 0; s < NSTAGE; s++) {
        if (s < NSTAGE - 1) {
            asm volatile("cp.async.wait_group 1;\n");
        } else {
            asm volatile("cp.async.wait_group 0;\n");
        }
        __syncthreads();
        if (s + 2 < NSTAGE) load_stage(bufl);

        const float* sp = smem + bufc * STAGE_WORDS;
#pragma unroll
        for (int cc = 0; cc < CC; cc++) {
            // in1: 4 px via one LDS.128 (conflict-free: starts 16r+4pc)
            float4 t1 = *(const float4*)(sp + cc * S1_CH + o1);
            F2U v1[NPAIR];
            v1[0].f2 = make_float2(t1.x, t1.y);
            v1[1].f2 = make_float2(t1.z, t1.w);

            // in2: 12-float span via 3 LDS.128 (conflict-free: stride 48 ≡ 16 mod 32)
            const float4* v2row = (const float4*)(sp + cc * S2_CH + o2);
            F2U v2[6];
#pragma unroll
            for (int q = 0; q < 3; q++) {
                float4 t = v2row[q];
                v2[2 * q].f2     = make_float2(t.x, t.y);
                v2[2 * q + 1].f2 = make_float2(t.z, t.w);
            }

            // even dw: packed FMA
#pragma unroll
            for (int k = 0; k < NPAIR; k++)
#pragma unroll
                for (int dh = 0; dh < 5; dh++)
                    fma2(accE[k][dh], v1[k].u, v2[k + dh].u);

            // odd dw: scalar FMAs on named halves
#pragma unroll
            for (int k = 0; k < NPAIR; k++)
#pragma unroll
                for (int dh = 0; dh < 4; dh++) {
                    accO[k][dh][0] = __fmaf_rn(v1[k].f2.x, v2[k + dh].f2.y, accO[k][dh][0]);
                    accO[k][dh][1] = __fmaf_rn(v1[k].f2.y, v2[k + dh + 1].f2.x, accO[k][dh][1]);
                }
        }

        bufc = (bufc == NBUF - 1) ? 0 : bufc + 1;
        bufl = (bufl == NBUF - 1) ? 0 : bufl + 1;
    }

    // epilogue
    const size_t plane = (size_t)H_DIM * W_DIM;
    float* op = out + (size_t)(b * 81 + ph * 9) * plane +
                (size_t)(h0 + r) * W_DIM + (w0 + x0);
#pragma unroll
    for (int dh = 0; dh < 5; dh++) {
        u64* orow = (u64*)(op + (size_t)(2 * dh) * plane);
#pragma unroll
        for (int k = 0; k < NPAIR; k++) orow[k] = accE[k][dh];
    }
#pragma unroll
    for (int dh = 0; dh < 4; dh++) {
        float* orow = op + (size_t)(2 * dh + 1) * plane;
#pragma unroll
        for (int k = 0; k < NPAIR; k++) {
            F2U t; t.f2.x = accO[k][dh][0]; t.f2.y = accO[k][dh][1];
            *(u64*)(orow + 2 * k) = t.u;
        }
    }
}

extern "C" void kernel_launch(void* const* d_in, const int* in_sizes, int n_in,
                              void* d_out, int out_size) {
    const float* in1 = (const float*)d_in[0];
    const float* in2 = (const float*)d_in[1];
    float* out = (float*)d_out;
    int Bn = in_sizes[0] / (C_DIM * H_DIM * W_DIM);
    size_t smem_bytes = (size_t)NBUF * STAGE_BYTES;  // 43008
    cudaFuncSetAttribute(corr_kernel, cudaFuncAttributeMaxDynamicSharedMemorySize,
                         (int)smem_bytes);
    dim3 grid(W_DIM / TW, H_DIM / TH, Bn);
    corr_kernel<<<grid, NTHREADS, smem_bytes>>>(in1, in2, out);
}

// round 17
// speedup vs baseline: 1.7475x; 1.0015x over previous
#include <cuda_runtime.h>
#include <cstdint>
#include <cstddef>

#define C_DIM 256
#define H_DIM 96
#define W_DIM 96
#define TW 16
#define TH 8
#define NPAIR 2
#define RAD 4
#define CC 4
#define NSTAGE (C_DIM / CC)                  // 64
#define S1_ROW 16
#define S1_CH  (TH * S1_ROW)                 // 128
#define S1_WORDS (CC * S1_CH)                // 512
#define S2_ROWS (TH + 8)                     // 16
#define S2_ROW 48                            // stride ≡ 16 mod 32 -> LDS.128 conflict-free
#define S2_CH  (S2_ROWS * S2_ROW)            // 768
#define S2_WORDS (CC * S2_CH)                // 3072
#define STAGE_WORDS (S1_WORDS + S2_WORDS)    // 3584
#define STAGE_BYTES (STAGE_WORDS * 4)        // 14336
#define NBUF 3
#define NTHREADS 288
#define CADV (CC * H_DIM * W_DIM)            // channel advance per stage (floats)

typedef unsigned long long u64;

union F2U { float2 f2; u64 u; };

__device__ __forceinline__ void fma2(u64 &d, u64 a, u64 b) {
    asm("fma.rn.f32x2 %0, %1, %2, %0;" : "+l"(d) : "l"(a), "l"(b));
}
__device__ __forceinline__ void cp16(uint32_t s, const float* g, uint32_t vbit) {
    int sz = vbit ? 16 : 0;
    asm volatile("cp.async.cg.shared.global [%0], [%1], 16, %2;\n"
                 :: "r"(s), "l"(g), "r"(sz));
}

__global__ __launch_bounds__(NTHREADS, 3)
void corr_kernel(const float* __restrict__ in1, const float* __restrict__ in2,
                 float* __restrict__ out) {
    extern __shared__ float smem[];
    const int tid = threadIdx.x;
    const int w0 = blockIdx.x * TW;
    const int h0 = blockIdx.y * TH;
    const int b  = blockIdx.z;

    const int ph   = tid >> 5;          // warp id = displacement row 0..8
    const int lane = tid & 31;
    const int pc   = lane & 3;          // 4-px block 0..3
    const int r    = lane >> 2;         // tile row 0..7
    const int x0   = pc * 4;

    // ---- hoisted load addressing ----
    // tid 0..127  : in2, 3x 16B chunks (half of one 24-float halo row)
    // tid 128..255: in1, 1x 16B chunk
    const bool l2ok = (tid < 128);
    const bool l1ok = (tid >= 128) && (tid < 256);
    const float* p1 = in1;
    const float* p2 = in2;
    uint32_t d1 = 0, d2 = 0, mask = 0;
    int adj = 0;
    if (l1ok) {
        const int t    = tid - 128;
        const int c1   = t >> 5;              // 0..3
        const int rem  = t & 31;
        const int row1 = rem >> 2;            // 0..7
        const int q    = rem & 3;             // 0..3
        p1 = in1 + (((size_t)(b * C_DIM + c1) * H_DIM + (h0 + row1)) * W_DIM + w0 + q * 4);
        d1 = (uint32_t)((c1 * S1_CH + row1 * S1_ROW + q * 4) * 4);
    }
    if (l2ok) {
        const int c2   = tid >> 5;            // 0..3
        const int rid  = tid & 31;
        const int y    = rid >> 1;            // 0..15
        const int half = rid & 1;
        const int h2   = h0 + y - RAD;
        const int col0 = w0 - RAD + half * 12;
        const bool hv  = (h2 >= 0) && (h2 < H_DIM);
#pragma unroll
        for (int j = 0; j < 3; j++) {
            int cg = col0 + 4 * j;
            if (hv && cg >= 0 && cg + 4 <= W_DIM) mask |= (1u << j);
        }
        const int wc = (col0 < 0) ? 0 : (col0 > W_DIM - 4 ? W_DIM - 4 : col0);
        adj = col0 - wc;
        p2 = in2 + (((size_t)(b * C_DIM + c2) * H_DIM + (hv ? h2 : 0)) * W_DIM + wc);
        d2 = (uint32_t)((S1_WORDS + c2 * S2_CH + y * S2_ROW + half * 12) * 4);
    }

    u64 accE[NPAIR][5];
    float accO[NPAIR][4][2];
#pragma unroll
    for (int k = 0; k < NPAIR; k++) {
#pragma unroll
        for (int d = 0; d < 5; d++) accE[k][d] = 0ull;
#pragma unroll
        for (int d = 0; d < 4; d++) { accO[k][d][0] = 0.f; accO[k][d][1] = 0.f; }
    }

    const uint32_t sb0 = (uint32_t)__cvta_generic_to_shared(smem);

    auto load_stage = [&](int buf) {
        const uint32_t sbase = sb0 + (uint32_t)(buf * STAGE_BYTES);
        if (l1ok) {
            cp16(sbase + d1, p1, 1u);
            p1 += CADV;
        }
        if (l2ok) {
#pragma unroll
            for (int j = 0; j < 3; j++) {
                uint32_t v = (mask >> j) & 1u;
                const float* src = p2 + (v ? (4 * j + adj) : 0);
                cp16(sbase + d2 + j * 16, src, v);
            }
            p2 += CADV;
        }
        asm volatile("cp.async.commit_group;\n");
    };

    load_stage(0);
    load_stage(1);

    // per-thread compute offsets (words) — immediates per channel
    const int o1 = r * S1_ROW + x0;
    const int y0 = r + ph;
    const int o2 = S1_WORDS + y0 * S2_ROW + x0;

    int bufc = 0;
    int bufl = 2;
    for (int s = 0; s < NSTAGE; s++) {
        if (s < NSTAGE - 1) {
            asm volatile("cp.async.wait_group 1;\n");
        } else {
            asm volatile("cp.async.wait_group 0;\n");
        }
        __syncthreads();
        if (s + 2 < NSTAGE) load_stage(bufl);

        const float* sp = smem + bufc * STAGE_WORDS;
#pragma unroll
        for (int cc = 0; cc < CC; cc++) {
            // in1: 4 px via one LDS.128 (conflict-free: starts 16r+4pc)
            float4 t1 = *(const float4*)(sp + cc * S1_CH + o1);
            F2U v1[NPAIR];
            v1[0].f2 = make_float2(t1.x, t1.y);
            v1[1].f2 = make_float2(t1.z, t1.w);

            // in2: 12-float span via 3 LDS.128 (conflict-free: stride 48 ≡ 16 mod 32)
            const float4* v2row = (const float4*)(sp + cc * S2_CH + o2);
            F2U v2[6];
#pragma unroll
            for (int q = 0; q < 3; q++) {
                float4 t = v2row[q];
                v2[2 * q].f2     = make_float2(t.x, t.y);
                v2[2 * q + 1].f2 = make_float2(t.z, t.w);
            }

            // even dw: packed FMA
#pragma unroll
            for (int k = 0; k < NPAIR; k++)
#pragma unroll
                for (int dh = 0; dh < 5; dh++)
                    fma2(accE[k][dh], v1[k].u, v2[k + dh].u);

            // odd dw: scalar FMAs on named halves
#pragma unroll
            for (int k = 0; k < NPAIR; k++)
#pragma unroll
                for (int dh = 0; dh < 4; dh++) {
                    accO[k][dh][0] = __fmaf_rn(v1[k].f2.x, v2[k + dh].f2.y, accO[k][dh][0]);
                    accO[k][dh][1] = __fmaf_rn(v1[k].f2.y, v2[k + dh + 1].f2.x, accO[k][dh][1]);
                }
        }

        bufc = (bufc == NBUF - 1) ? 0 : bufc + 1;
        bufl = (bufl == NBUF - 1) ? 0 : bufl + 1;
    }

    // epilogue
    const size_t plane = (size_t)H_DIM * W_DIM;
    float* op = out + (size_t)(b * 81 + ph * 9) * plane +
                (size_t)(h0 + r) * W_DIM + (w0 + x0);
#pragma unroll
    for (int dh = 0; dh < 5; dh++) {
        u64* orow = (u64*)(op + (size_t)(2 * dh) * plane);
#pragma unroll
        for (int k = 0; k < NPAIR; k++) orow[k] = accE[k][dh];
    }
#pragma unroll
    for (int dh = 0; dh < 4; dh++) {
        float* orow = op + (size_t)(2 * dh + 1) * plane;
#pragma unroll
        for (int k = 0; k < NPAIR; k++) {
            F2U t; t.f2.x = accO[k][dh][0]; t.f2.y = accO[k][dh][1];
            *(u64*)(orow + 2 * k) = t.u;
        }
    }
}

extern "C" void kernel_launch(void* const* d_in, const int* in_sizes, int n_in,
                              void* d_out, int out_size) {
    const float* in1 = (const float*)d_in[0];
    const float* in2 = (const float*)d_in[1];
    float* out = (float*)d_out;
    int Bn = in_sizes[0] / (C_DIM * H_DIM * W_DIM);
    size_t smem_bytes = (size_t)NBUF * STAGE_BYTES;  // 43008
    cudaFuncSetAttribute(corr_kernel, cudaFuncAttributeMaxDynamicSharedMemorySize,
                         (int)smem_bytes);
    dim3 grid(W_DIM / TW, H_DIM / TH, Bn);
    corr_kernel<<<grid, NTHREADS, smem_bytes>>>(in1, in2, out);
}